// round 2
// baseline (speedup 1.0000x reference)
#include <cuda_runtime.h>
#include <math.h>

// Problem constants
#define BSZ 8
#define SEQ 1024
#define DM  512
#define NH  8
#define HD  64
#define NEGV (-1e9f)

// ---------------------------------------------------------------------------
// Scratch (static device globals)
// ---------------------------------------------------------------------------
__device__ float g_q  [(size_t)BSZ * NH * SEQ * HD];   // [b,h,s,d]
__device__ float g_kT [(size_t)BSZ * NH * HD * SEQ];   // [b,h,d,s]
__device__ float g_v  [(size_t)BSZ * NH * SEQ * HD];   // [b,h,s,d]
__device__ float g_ctx[(size_t)BSZ * SEQ * DM];        // [b*s, h*dv]
__device__ float g_pre[(size_t)BSZ * SEQ * DM];        // pre-LN
__device__ float g_attn_fb[(size_t)BSZ * NH * SEQ * SEQ]; // fallback if attn not in d_out

// ---------------------------------------------------------------------------
// Projection GEMM: C = A[M,K] @ W[K,N] + bias, M=8192, N=K=512
// MODE 0: scatter to [b,h,s,d];  MODE 1: scatter to [b,h,d,s] (k transposed)
// MODE 2: row-major out + residual (output projection)
// ---------------------------------------------------------------------------
template<int MODE>
__global__ void __launch_bounds__(256)
gemm_proj(const float* __restrict__ A, const float* __restrict__ W,
          const float* __restrict__ bias, const float* __restrict__ resid,
          float* __restrict__ out)
{
    const int K = DM, N = DM;
    __shared__ float As[8][128];
    __shared__ float Bs[8][128];
    int tid = threadIdx.x;
    int tx = tid & 15, ty = tid >> 4;
    int m0 = blockIdx.y * 128, n0 = blockIdx.x * 128;

    float acc[8][8];
#pragma unroll
    for (int i = 0; i < 8; i++)
#pragma unroll
        for (int j = 0; j < 8; j++) acc[i][j] = 0.f;

    int a_row = tid >> 1, a_col = (tid & 1) * 4;
    int b_row = tid >> 5, b_col = (tid & 31) * 4;
    const float* Ag = A + (size_t)(m0 + a_row) * K + a_col;
    const float* Bg = W + (size_t)b_row * N + n0 + b_col;

    for (int k0 = 0; k0 < K; k0 += 8) {
        float4 av = *(const float4*)(Ag + k0);
        float4 bv = *(const float4*)(Bg + (size_t)k0 * N);
        As[a_col + 0][a_row] = av.x;
        As[a_col + 1][a_row] = av.y;
        As[a_col + 2][a_row] = av.z;
        As[a_col + 3][a_row] = av.w;
        *(float4*)&Bs[b_row][b_col] = bv;
        __syncthreads();
#pragma unroll
        for (int k = 0; k < 8; k++) {
            float a[8], b[8];
            *(float4*)(a)     = *(const float4*)&As[k][ty * 8];
            *(float4*)(a + 4) = *(const float4*)&As[k][ty * 8 + 4];
            *(float4*)(b)     = *(const float4*)&Bs[k][tx * 8];
            *(float4*)(b + 4) = *(const float4*)&Bs[k][tx * 8 + 4];
#pragma unroll
            for (int i = 0; i < 8; i++)
#pragma unroll
                for (int j = 0; j < 8; j++)
                    acc[i][j] = fmaf(a[i], b[j], acc[i][j]);
        }
        __syncthreads();
    }

#pragma unroll
    for (int i = 0; i < 8; i++) {
        int m = m0 + ty * 8 + i;
#pragma unroll
        for (int j = 0; j < 8; j++) {
            int n = n0 + tx * 8 + j;
            float v = acc[i][j] + bias[n];
            if (MODE == 2) {
                out[(size_t)m * DM + n] = v + resid[(size_t)m * DM + n];
            } else {
                int b_ = m >> 10, s = m & (SEQ - 1);
                int h  = n >> 6,  d = n & (HD - 1);
                if (MODE == 0)
                    out[(((size_t)(b_ * NH + h) * SEQ + s) << 6) + d] = v;
                else
                    out[(((size_t)(b_ * NH + h) * HD + d) << 10) + s] = v;
            }
        }
    }
}

// ---------------------------------------------------------------------------
// Score GEMM (batched over b*h): S = q[1024,64] @ kT[64,1024] / 8,
// masked_fill (mask is INT32 on device), + adjoin.
// ---------------------------------------------------------------------------
__global__ void __launch_bounds__(256)
gemm_scores(const float* __restrict__ q, const float* __restrict__ kT,
            const int* __restrict__ mask,
            const float* __restrict__ adjoin,
            float* __restrict__ scores)
{
    int bh = blockIdx.z;
    int b_ = bh >> 3;
    const float* A  = q  + (size_t)bh * SEQ * HD;
    const float* Bm = kT + (size_t)bh * HD * SEQ;
    float* out = scores + (size_t)bh * SEQ * SEQ;

    __shared__ float As[8][128];
    __shared__ float Bs[8][128];
    int tid = threadIdx.x;
    int tx = tid & 15, ty = tid >> 4;
    int m0 = blockIdx.y * 128, n0 = blockIdx.x * 128;

    float acc[8][8];
#pragma unroll
    for (int i = 0; i < 8; i++)
#pragma unroll
        for (int j = 0; j < 8; j++) acc[i][j] = 0.f;

    int a_row = tid >> 1, a_col = (tid & 1) * 4;
    int b_row = tid >> 5, b_col = (tid & 31) * 4;

    for (int k0 = 0; k0 < HD; k0 += 8) {
        float4 av = *(const float4*)(A + (size_t)(m0 + a_row) * HD + k0 + a_col);
        float4 bv = *(const float4*)(Bm + (size_t)(k0 + b_row) * SEQ + n0 + b_col);
        As[a_col + 0][a_row] = av.x;
        As[a_col + 1][a_row] = av.y;
        As[a_col + 2][a_row] = av.z;
        As[a_col + 3][a_row] = av.w;
        *(float4*)&Bs[b_row][b_col] = bv;
        __syncthreads();
#pragma unroll
        for (int k = 0; k < 8; k++) {
            float a[8], b[8];
            *(float4*)(a)     = *(const float4*)&As[k][ty * 8];
            *(float4*)(a + 4) = *(const float4*)&As[k][ty * 8 + 4];
            *(float4*)(b)     = *(const float4*)&Bs[k][tx * 8];
            *(float4*)(b + 4) = *(const float4*)&Bs[k][tx * 8 + 4];
#pragma unroll
            for (int i = 0; i < 8; i++)
#pragma unroll
                for (int j = 0; j < 8; j++)
                    acc[i][j] = fmaf(a[i], b[j], acc[i][j]);
        }
        __syncthreads();
    }

    const int*   mb = mask   + (size_t)b_ * SEQ * SEQ;
    const float* ab = adjoin + (size_t)b_ * SEQ * SEQ;
#pragma unroll
    for (int i = 0; i < 8; i++) {
        int m = m0 + ty * 8 + i;
        size_t roff = (size_t)m * SEQ;
#pragma unroll
        for (int j = 0; j < 8; j++) {
            int n = n0 + tx * 8 + j;
            float sv = acc[i][j] * 0.125f;   // 1/sqrt(64)
            if (mb[roff + n] != 0) sv = NEGV;  // mask BEFORE adjoin (matches ref)
            sv += ab[roff + n];
            out[roff + n] = sv;
        }
    }
}

// ---------------------------------------------------------------------------
// Softmax: one warp per row of 1024, in place.
// ---------------------------------------------------------------------------
__global__ void __launch_bounds__(256)
softmax_rows(float* __restrict__ scores)
{
    int warp = threadIdx.x >> 5, lane = threadIdx.x & 31;
    size_t row = (size_t)blockIdx.x * 8 + warp;
    float* p = scores + row * SEQ;

    float x[32];
    float mx = -INFINITY;
#pragma unroll
    for (int i = 0; i < 8; i++) {
        float4 v = *(const float4*)(p + i * 128 + lane * 4);
        x[i * 4 + 0] = v.x; x[i * 4 + 1] = v.y;
        x[i * 4 + 2] = v.z; x[i * 4 + 3] = v.w;
        mx = fmaxf(mx, fmaxf(fmaxf(v.x, v.y), fmaxf(v.z, v.w)));
    }
#pragma unroll
    for (int o = 16; o; o >>= 1) mx = fmaxf(mx, __shfl_xor_sync(0xffffffffu, mx, o));

    float sum = 0.f;
#pragma unroll
    for (int i = 0; i < 32; i++) { x[i] = __expf(x[i] - mx); sum += x[i]; }
#pragma unroll
    for (int o = 16; o; o >>= 1) sum += __shfl_xor_sync(0xffffffffu, sum, o);

    float inv = 1.f / sum;
#pragma unroll
    for (int i = 0; i < 8; i++) {
        float4 v;
        v.x = x[i * 4 + 0] * inv; v.y = x[i * 4 + 1] * inv;
        v.z = x[i * 4 + 2] * inv; v.w = x[i * 4 + 3] * inv;
        *(float4*)(p + i * 128 + lane * 4) = v;
    }
}

// ---------------------------------------------------------------------------
// Context GEMM (batched over b*h): ctx = attn[1024,1024] @ v[1024,64]
// ---------------------------------------------------------------------------
__global__ void __launch_bounds__(256)
gemm_ctx(const float* __restrict__ attn, const float* __restrict__ v,
         float* __restrict__ ctx)
{
    int bh = blockIdx.z;
    int b_ = bh >> 3, h = bh & 7;
    const float* A  = attn + (size_t)bh * SEQ * SEQ;  // lda=SEQ
    const float* Bm = v    + (size_t)bh * SEQ * HD;   // ldb=HD
    int m0 = blockIdx.y * 128;

    __shared__ float As[16][128];
    __shared__ float Bs[16][64];
    int tid = threadIdx.x;
    int tx = tid & 15, ty = tid >> 4;

    float acc[8][4];
#pragma unroll
    for (int i = 0; i < 8; i++)
#pragma unroll
        for (int j = 0; j < 4; j++) acc[i][j] = 0.f;

    for (int k0 = 0; k0 < SEQ; k0 += 16) {
#pragma unroll
        for (int l = 0; l < 2; l++) {
            int idx = tid + l * 256;
            int row = idx >> 2, cq = (idx & 3) * 4;
            float4 av = *(const float4*)(A + (size_t)(m0 + row) * SEQ + k0 + cq);
            As[cq + 0][row] = av.x;
            As[cq + 1][row] = av.y;
            As[cq + 2][row] = av.z;
            As[cq + 3][row] = av.w;
        }
        {
            int brow = tid >> 4, bcol = (tid & 15) * 4;
            *(float4*)&Bs[brow][bcol] =
                *(const float4*)(Bm + (size_t)(k0 + brow) * HD + bcol);
        }
        __syncthreads();
#pragma unroll
        for (int k = 0; k < 16; k++) {
            float a[8], bb[4];
            *(float4*)(a)     = *(const float4*)&As[k][ty * 8];
            *(float4*)(a + 4) = *(const float4*)&As[k][ty * 8 + 4];
            *(float4*)(bb)    = *(const float4*)&Bs[k][tx * 4];
#pragma unroll
            for (int i = 0; i < 8; i++)
#pragma unroll
                for (int j = 0; j < 4; j++)
                    acc[i][j] = fmaf(a[i], bb[j], acc[i][j]);
        }
        __syncthreads();
    }

#pragma unroll
    for (int i = 0; i < 8; i++) {
        int m = m0 + ty * 8 + i;
        float4 w;
        w.x = acc[i][0]; w.y = acc[i][1]; w.z = acc[i][2]; w.w = acc[i][3];
        *(float4*)&ctx[((size_t)(b_ * SEQ + m)) * DM + h * HD + tx * 4] = w;
    }
}

// ---------------------------------------------------------------------------
// LayerNorm: one warp per row of 512, eps=1e-6
// ---------------------------------------------------------------------------
__global__ void __launch_bounds__(256)
layernorm_rows(const float* __restrict__ pre, const float* __restrict__ g,
               const float* __restrict__ be, float* __restrict__ out)
{
    int warp = threadIdx.x >> 5, lane = threadIdx.x & 31;
    size_t row = (size_t)blockIdx.x * 8 + warp;
    const float* p = pre + row * DM;

    float x[16];
    float s = 0.f, s2 = 0.f;
#pragma unroll
    for (int i = 0; i < 4; i++) {
        float4 v = *(const float4*)(p + i * 128 + lane * 4);
        x[i * 4 + 0] = v.x; x[i * 4 + 1] = v.y;
        x[i * 4 + 2] = v.z; x[i * 4 + 3] = v.w;
        s  += v.x + v.y + v.z + v.w;
        s2 += v.x * v.x + v.y * v.y + v.z * v.z + v.w * v.w;
    }
#pragma unroll
    for (int o = 16; o; o >>= 1) {
        s  += __shfl_xor_sync(0xffffffffu, s,  o);
        s2 += __shfl_xor_sync(0xffffffffu, s2, o);
    }
    float mu  = s  * (1.f / DM);
    float var = s2 * (1.f / DM) - mu * mu;
    float inv = rsqrtf(var + 1e-6f);

    float* po = out + row * DM;
#pragma unroll
    for (int i = 0; i < 4; i++) {
        float4 w;
        int c = i * 128 + lane * 4;
        w.x = (x[i * 4 + 0] - mu) * inv * g[c + 0] + be[c + 0];
        w.y = (x[i * 4 + 1] - mu) * inv * g[c + 1] + be[c + 1];
        w.z = (x[i * 4 + 2] - mu) * inv * g[c + 2] + be[c + 2];
        w.w = (x[i * 4 + 3] - mu) * inv * g[c + 3] + be[c + 3];
        *(float4*)(po + c) = w;
    }
}

// ---------------------------------------------------------------------------
// Launch
// ---------------------------------------------------------------------------
extern "C" void kernel_launch(void* const* d_in, const int* in_sizes, int n_in,
                              void* d_out, int out_size)
{
    const float* Q   = (const float*)d_in[0];
    const float* K   = (const float*)d_in[1];
    const float* V   = (const float*)d_in[2];
    const int*   mask = (const int*)d_in[3];   // bool materialized as int32
    const float* adjoin = (const float*)d_in[4];
    const float* Wq = (const float*)d_in[5];
    const float* bq = (const float*)d_in[6];
    const float* Wk = (const float*)d_in[7];
    const float* bk = (const float*)d_in[8];
    const float* Wv = (const float*)d_in[9];
    const float* bv = (const float*)d_in[10];
    const float* Wo = (const float*)d_in[11];
    const float* bo = (const float*)d_in[12];
    const float* lg = (const float*)d_in[13];
    const float* lb = (const float*)d_in[14];

    float *qb, *kb, *vb, *cb, *pb, *afb;
    cudaGetSymbolAddress((void**)&qb,  g_q);
    cudaGetSymbolAddress((void**)&kb,  g_kT);
    cudaGetSymbolAddress((void**)&vb,  g_v);
    cudaGetSymbolAddress((void**)&cb,  g_ctx);
    cudaGetSymbolAddress((void**)&pb,  g_pre);
    cudaGetSymbolAddress((void**)&afb, g_attn_fb);

    float* out0 = (float*)d_out;
    const size_t OUT0 = (size_t)BSZ * SEQ * DM;               // 4,194,304
    const size_t ATTN = (size_t)BSZ * NH * SEQ * SEQ;         // 67,108,864
    // Reference returns (out, attn): write attn into d_out after out if it fits.
    float* attn = ((size_t)out_size >= OUT0 + ATTN) ? (out0 + OUT0) : afb;

    // 1) Projections (q, v in [b,h,s,d]; k transposed to [b,h,d,s])
    dim3 gp(DM / 128, (BSZ * SEQ) / 128);      // (4, 64)
    gemm_proj<0><<<gp, 256>>>(Q, Wq, bq, nullptr, qb);
    gemm_proj<1><<<gp, 256>>>(K, Wk, bk, nullptr, kb);
    gemm_proj<0><<<gp, 256>>>(V, Wv, bv, nullptr, vb);

    // 2) Scores + scale + mask + adjoin
    dim3 gs(SEQ / 128, SEQ / 128, BSZ * NH);   // (8, 8, 64)
    gemm_scores<<<gs, 256>>>(qb, kb, mask, adjoin, attn);

    // 3) Softmax in place (this IS the attn output)
    softmax_rows<<<(BSZ * NH * SEQ) / 8, 256>>>(attn);

    // 4) Context
    dim3 gc(1, SEQ / 128, BSZ * NH);           // (1, 8, 64)
    gemm_ctx<<<gc, 256>>>(attn, vb, cb);

    // 5) Output projection + bias + residual(Q)
    gemm_proj<2><<<gp, 256>>>(cb, Wo, bo, Q, pb);

    // 6) LayerNorm -> out
    layernorm_rows<<<(BSZ * SEQ) / 8, 256>>>(pb, lg, lb, out0);
}